// round 4
// baseline (speedup 1.0000x reference)
#include <cuda_runtime.h>
#include <cuda_bf16.h>

#define NU 100000
#define NI 100000
#define DD 64
#define NN (NU + NI)
#define NL 3

// Scratch buffers (allowed as __device__ globals). 3 x 51.2 MB.
__device__ float g_bufA[(size_t)NN * DD];  // current layer embedding (input to SpMM)
__device__ float g_bufB[(size_t)NN * DD];  // SpMM output accumulator
__device__ float g_acc [(size_t)NN * DD];  // running sum over layers

__device__ __forceinline__ float sigmoidf_(float x) {
    return 1.0f / (1.0f + __expf(-x));
}

// ---------------------------------------------------------------------------
// Layer-0 semantic fusion: bufA = fuse(emb, side), acc = bufA, bufB = 0.
// One thread per float4. NN*16 = 3.2M threads.
// ---------------------------------------------------------------------------
__global__ void __launch_bounds__(256)
fuse0_kernel(const float4* __restrict__ ue,
             const float4* __restrict__ ie,
             const float4* __restrict__ se,
             const float4* __restrict__ he,
             const float* __restrict__ ulw,
             const float* __restrict__ ilw) {
    int i = blockIdx.x * blockDim.x + threadIdx.x;
    const int total = NN * (DD / 4);
    if (i >= total) return;
    int row = i >> 4;  // D/4 = 16 float4s per row
    float4 x, s;
    float w;
    if (row < NU) {
        w = sigmoidf_(ulw[0]);
        x = ue[i];
        s = se[i];
    } else {
        w = sigmoidf_(ilw[0]);
        int j = i - NU * (DD / 4);
        x = ie[j];
        s = he[j];
    }
    float iw = 1.0f - w;
    float4 o;
    o.x = w * x.x + iw * s.x;
    o.y = w * x.y + iw * s.y;
    o.z = w * x.z + iw * s.z;
    o.w = w * x.w + iw * s.w;
    reinterpret_cast<float4*>(g_bufA)[i] = o;
    reinterpret_cast<float4*>(g_acc)[i] = o;
    reinterpret_cast<float4*>(g_bufB)[i] = make_float4(0.f, 0.f, 0.f, 0.f);
}

// ---------------------------------------------------------------------------
// SpMM: bufB[row] += val * bufA[col] for each edge.
// 16 threads per edge-slot, one float4 each; each thread processes TWO edges
// (e and e + Ehalf) for doubled memory-level parallelism. Vectorized
// red.global.add.v4.f32 (sm_90+). Edge streams loaded evict-first (__ldcs)
// so the resident embedding buffers (bufA+bufB, ~102 MB) stay in L2 (126 MB).
// ---------------------------------------------------------------------------
__global__ void __launch_bounds__(256)
spmm_kernel(const float* __restrict__ ev,
            const int* __restrict__ er,
            const int* __restrict__ ec,
            int E, int Ehalf) {
    long long t = (long long)blockIdx.x * blockDim.x + threadIdx.x;
    long long slots = (long long)Ehalf * 16;
    if (t >= slots) return;
    int e0 = (int)(t >> 4);
    int c  = ((int)t & 15) << 2;  // float offset within row: 0,4,...,60
    int e1 = e0 + Ehalf;          // second edge (may be >= E for last thread group)

    // --- edge 0 ---
    int   col0 = __ldcs(ec + e0);
    int   row0 = __ldcs(er + e0);
    float v0   = __ldcs(ev + e0);
    const float4 x0 = *reinterpret_cast<const float4*>(
        g_bufA + (unsigned)col0 * DD + c);

    // --- edge 1 (issue gather before first RED for MLP) ---
    bool has1 = (e1 < E);
    int col1 = 0, row1 = 0;
    float v1 = 0.f;
    float4 x1 = make_float4(0.f, 0.f, 0.f, 0.f);
    if (has1) {
        col1 = __ldcs(ec + e1);
        row1 = __ldcs(er + e1);
        v1   = __ldcs(ev + e1);
        x1 = *reinterpret_cast<const float4*>(
            g_bufA + (unsigned)col1 * DD + c);
    }

    {
        float* yp = g_bufB + (unsigned)row0 * DD + c;
        float m0 = v0 * x0.x, m1 = v0 * x0.y, m2 = v0 * x0.z, m3 = v0 * x0.w;
        asm volatile("red.global.add.v4.f32 [%0], {%1, %2, %3, %4};"
                     :: "l"(yp), "f"(m0), "f"(m1), "f"(m2), "f"(m3)
                     : "memory");
    }
    if (has1) {
        float* yp = g_bufB + (unsigned)row1 * DD + c;
        float m0 = v1 * x1.x, m1 = v1 * x1.y, m2 = v1 * x1.z, m3 = v1 * x1.w;
        asm volatile("red.global.add.v4.f32 [%0], {%1, %2, %3, %4};"
                     :: "l"(yp), "f"(m0), "f"(m1), "f"(m2), "f"(m3)
                     : "memory");
    }
}

// ---------------------------------------------------------------------------
// Per-layer fusion: bufA = w*bufB + (1-w)*side, acc += bufA, bufB = 0
// (re-zeroed in the same pass for the next SpMM layer).
// ---------------------------------------------------------------------------
__global__ void __launch_bounds__(256)
fuse_layer_kernel(const float4* __restrict__ se,
                  const float4* __restrict__ he,
                  const float* __restrict__ ulw,
                  const float* __restrict__ ilw,
                  int layer) {
    int i = blockIdx.x * blockDim.x + threadIdx.x;
    const int total = NN * (DD / 4);
    if (i >= total) return;
    int row = i >> 4;
    float4 y = reinterpret_cast<const float4*>(g_bufB)[i];
    float4 s;
    float w;
    if (row < NU) {
        w = sigmoidf_(ulw[layer]);
        s = se[i];
    } else {
        w = sigmoidf_(ilw[layer]);
        s = he[i - NU * (DD / 4)];
    }
    float iw = 1.0f - w;
    float4 o;
    o.x = w * y.x + iw * s.x;
    o.y = w * y.y + iw * s.y;
    o.z = w * y.z + iw * s.z;
    o.w = w * y.w + iw * s.w;
    reinterpret_cast<float4*>(g_bufA)[i] = o;
    float4 a = reinterpret_cast<const float4*>(g_acc)[i];
    a.x += o.x; a.y += o.y; a.z += o.z; a.w += o.w;
    reinterpret_cast<float4*>(g_acc)[i] = a;
    reinterpret_cast<float4*>(g_bufB)[i] = make_float4(0.f, 0.f, 0.f, 0.f);
}

// ---------------------------------------------------------------------------
// gamma[b] = dot(acc[users[b]], acc[U+items[b]]) / (L+1)^2
// One warp per (user,item) pair; lane reads float2 from each row.
// ---------------------------------------------------------------------------
__global__ void __launch_bounds__(256)
dot_kernel(const int* __restrict__ users,
           const int* __restrict__ items,
           float* __restrict__ out,
           int B) {
    int gid = blockIdx.x * blockDim.x + threadIdx.x;
    int w = gid >> 5;
    int lane = threadIdx.x & 31;
    if (w >= B) return;
    int u  = __ldg(users + w);
    int it = __ldg(items + w);
    const float2* up = reinterpret_cast<const float2*>(g_acc + (unsigned)u * DD);
    const float2* ip = reinterpret_cast<const float2*>(g_acc + (unsigned)(NU + it) * DD);
    float2 a = up[lane];
    float2 b = ip[lane];
    float s = a.x * b.x + a.y * b.y;
    #pragma unroll
    for (int o = 16; o > 0; o >>= 1)
        s += __shfl_down_sync(0xffffffffu, s, o);
    if (lane == 0) out[w] = s * (1.0f / ((NL + 1) * (NL + 1)));
}

// ---------------------------------------------------------------------------
// kernel_launch
// Inputs (metadata order):
//  0 user_emb [U*D] f32    1 item_emb [I*D] f32
//  2 symptom_emb [U*D] f32 3 herb_emb [I*D] f32
//  4 user_lw [L+1] f32     5 item_lw [L+1] f32
//  6 edge_val [E] f32      7 edge_row [E] i32   8 edge_col [E] i32
//  9 users [B] i32        10 items [B] i32
// Output: gamma [B] f32
// ---------------------------------------------------------------------------
extern "C" void kernel_launch(void* const* d_in, const int* in_sizes, int n_in,
                              void* d_out, int out_size) {
    const float4* ue  = (const float4*)d_in[0];
    const float4* ie  = (const float4*)d_in[1];
    const float4* se  = (const float4*)d_in[2];
    const float4* he  = (const float4*)d_in[3];
    const float*  ulw = (const float*)d_in[4];
    const float*  ilw = (const float*)d_in[5];
    const float*  ev  = (const float*)d_in[6];
    const int*    er  = (const int*)d_in[7];
    const int*    ec  = (const int*)d_in[8];
    const int*    us  = (const int*)d_in[9];
    const int*    it  = (const int*)d_in[10];
    float* out = (float*)d_out;

    const int E = in_sizes[6];
    const int B = in_sizes[9];
    const int Ehalf = (E + 1) / 2;

    const int elem_threads = NN * (DD / 4);
    const int TB = 256;
    const int elem_blocks = (elem_threads + TB - 1) / TB;

    fuse0_kernel<<<elem_blocks, TB>>>(ue, ie, se, he, ulw, ilw);

    long long spmm_work = (long long)Ehalf * 16;
    int spmm_blocks = (int)((spmm_work + TB - 1) / TB);

    for (int layer = 1; layer <= NL; layer++) {
        spmm_kernel<<<spmm_blocks, TB>>>(ev, er, ec, E, Ehalf);
        fuse_layer_kernel<<<elem_blocks, TB>>>(se, he, ulw, ilw, layer);
    }

    int dot_blocks = (B * 32 + TB - 1) / TB;
    dot_kernel<<<dot_blocks, TB>>>(us, it, out, B);
}

// round 5
// speedup vs baseline: 1.6118x; 1.6118x over previous
#include <cuda_runtime.h>
#include <cuda_bf16.h>

#define NU 100000
#define NI 100000
#define DD 64
#define NN (NU + NI)
#define NL 3
#define EMAX 6400000
#define CHUNK 1024
#define NCHUNK ((NN + CHUNK - 1) / CHUNK)   // 196

// Scratch (device globals per the allocation rules).
__device__ float g_bufA[(size_t)NN * DD];   // ping
__device__ float g_bufB[(size_t)NN * DD];   // pong
__device__ float g_acc [(size_t)NN * DD];   // running layer sum
__device__ int2  g_csr [EMAX];              // (col, val-bits) grouped by row
__device__ int   g_rowstart[NN + 1];
__device__ int   g_counts[NN];
__device__ int   g_cursor[NN];
__device__ int   g_chunkSum[NCHUNK];
__device__ int   g_chunkOff[NCHUNK];

__device__ __forceinline__ float sigmoidf_(float x) {
    return 1.0f / (1.0f + __expf(-x));
}

// ---------------------------------------------------------------------------
// Layer-0 semantic fusion: bufA = fuse(emb, side), acc = bufA.
// ---------------------------------------------------------------------------
__global__ void __launch_bounds__(256)
fuse0_kernel(const float4* __restrict__ ue,
             const float4* __restrict__ ie,
             const float4* __restrict__ se,
             const float4* __restrict__ he,
             const float* __restrict__ ulw,
             const float* __restrict__ ilw) {
    int i = blockIdx.x * blockDim.x + threadIdx.x;
    const int total = NN * (DD / 4);
    if (i >= total) return;
    int row = i >> 4;
    float4 x, s;
    float w;
    if (row < NU) {
        w = sigmoidf_(ulw[0]);
        x = ue[i];
        s = se[i];
    } else {
        w = sigmoidf_(ilw[0]);
        int j = i - NU * (DD / 4);
        x = ie[j];
        s = he[j];
    }
    float iw = 1.0f - w;
    float4 o;
    o.x = w * x.x + iw * s.x;
    o.y = w * x.y + iw * s.y;
    o.z = w * x.z + iw * s.z;
    o.w = w * x.w + iw * s.w;
    reinterpret_cast<float4*>(g_bufA)[i] = o;
    reinterpret_cast<float4*>(g_acc)[i] = o;
}

// ---------------------------------------------------------------------------
// CSR build, step 0: zero counts + cursors.
// ---------------------------------------------------------------------------
__global__ void __launch_bounds__(256)
zero_counts_kernel() {
    int i = blockIdx.x * blockDim.x + threadIdx.x;
    if (i < NN) { g_counts[i] = 0; g_cursor[i] = 0; }
}

// ---------------------------------------------------------------------------
// CSR build, step 1: histogram of edge rows.
// ---------------------------------------------------------------------------
__global__ void __launch_bounds__(256)
hist_kernel(const int* __restrict__ er, int E) {
    int e = blockIdx.x * blockDim.x + threadIdx.x;
    if (e >= E) return;
    atomicAdd(&g_counts[__ldcs(er + e)], 1);
}

// ---------------------------------------------------------------------------
// CSR build, step 2a: per-chunk sums (CHUNK counts -> 1 sum).
// ---------------------------------------------------------------------------
__global__ void __launch_bounds__(CHUNK)
scan_reduce_kernel() {
    __shared__ int sh[CHUNK];
    int tid = threadIdx.x;
    int i = blockIdx.x * CHUNK + tid;
    sh[tid] = (i < NN) ? g_counts[i] : 0;
    __syncthreads();
    #pragma unroll
    for (int s = CHUNK / 2; s > 0; s >>= 1) {
        if (tid < s) sh[tid] += sh[tid + s];
        __syncthreads();
    }
    if (tid == 0) g_chunkSum[blockIdx.x] = sh[0];
}

// ---------------------------------------------------------------------------
// CSR build, step 2b: exclusive scan of chunk sums (single block, serial).
// ---------------------------------------------------------------------------
__global__ void scan_chunks_kernel(int E) {
    if (threadIdx.x == 0) {
        int run = 0;
        for (int c = 0; c < NCHUNK; c++) {
            g_chunkOff[c] = run;
            run += g_chunkSum[c];
        }
        g_rowstart[NN] = E;
    }
}

// ---------------------------------------------------------------------------
// CSR build, step 2c: intra-chunk exclusive scan + chunk offset -> rowstart.
// ---------------------------------------------------------------------------
__global__ void __launch_bounds__(CHUNK)
scan_final_kernel() {
    __shared__ int sh[CHUNK];
    int tid = threadIdx.x;
    int i = blockIdx.x * CHUNK + tid;
    int x = (i < NN) ? g_counts[i] : 0;
    sh[tid] = x;
    __syncthreads();
    // Hillis-Steele inclusive scan
    #pragma unroll
    for (int off = 1; off < CHUNK; off <<= 1) {
        int t = (tid >= off) ? sh[tid - off] : 0;
        __syncthreads();
        sh[tid] += t;
        __syncthreads();
    }
    if (i < NN) g_rowstart[i] = sh[tid] - x + g_chunkOff[blockIdx.x];
}

// ---------------------------------------------------------------------------
// CSR build, step 3: permute (col,val) into row-grouped order.
// ---------------------------------------------------------------------------
__global__ void __launch_bounds__(256)
permute_kernel(const float* __restrict__ ev,
               const int* __restrict__ er,
               const int* __restrict__ ec,
               int E) {
    int e = blockIdx.x * blockDim.x + threadIdx.x;
    if (e >= E) return;
    int r = __ldcs(er + e);
    int slot = atomicAdd(&g_cursor[r], 1);
    int pos = g_rowstart[r] + slot;
    g_csr[pos] = make_int2(__ldcs(ec + e), __float_as_int(__ldcs(ev + e)));
}

// ---------------------------------------------------------------------------
// Fused CSR SpMM + semantic fusion + acc update.
// One warp per row; lane owns dims [2*lane, 2*lane+1] (float2).
//   y[row] = sum_j val_j * in[col_j]           (register accumulation)
//   o = w*y + (1-w)*side;  out[row] = o;  acc[row] += o
// parity 0: in = bufA, out = bufB; parity 1: swapped.
// ---------------------------------------------------------------------------
__global__ void __launch_bounds__(256)
spmm_fuse_kernel(const float2* __restrict__ se,
                 const float2* __restrict__ he,
                 const float* __restrict__ ulw,
                 const float* __restrict__ ilw,
                 int layer, int parity) {
    int gw = (blockIdx.x * blockDim.x + threadIdx.x) >> 5;
    if (gw >= NN) return;
    int lane = threadIdx.x & 31;

    const float2* in  = reinterpret_cast<const float2*>(parity ? g_bufB : g_bufA);
    float2*       out = reinterpret_cast<float2*>(parity ? g_bufA : g_bufB);

    int beg = g_rowstart[gw];
    int end = g_rowstart[gw + 1];

    float2 acc = make_float2(0.f, 0.f);
    int j = beg;
    // unroll-4 for MLP
    for (; j + 4 <= end; j += 4) {
        int2 a0 = g_csr[j];
        int2 a1 = g_csr[j + 1];
        int2 a2 = g_csr[j + 2];
        int2 a3 = g_csr[j + 3];
        float2 x0 = __ldg(in + (unsigned)a0.x * 32 + lane);
        float2 x1 = __ldg(in + (unsigned)a1.x * 32 + lane);
        float2 x2 = __ldg(in + (unsigned)a2.x * 32 + lane);
        float2 x3 = __ldg(in + (unsigned)a3.x * 32 + lane);
        float v0 = __int_as_float(a0.y), v1 = __int_as_float(a1.y);
        float v2 = __int_as_float(a2.y), v3 = __int_as_float(a3.y);
        acc.x += v0 * x0.x; acc.y += v0 * x0.y;
        acc.x += v1 * x1.x; acc.y += v1 * x1.y;
        acc.x += v2 * x2.x; acc.y += v2 * x2.y;
        acc.x += v3 * x3.x; acc.y += v3 * x3.y;
    }
    for (; j < end; j++) {
        int2 a = g_csr[j];
        float2 x = __ldg(in + (unsigned)a.x * 32 + lane);
        float v = __int_as_float(a.y);
        acc.x += v * x.x; acc.y += v * x.y;
    }

    // semantic fusion epilogue
    float w;
    float2 s;
    if (gw < NU) {
        w = sigmoidf_(__ldg(ulw + layer));
        s = se[(unsigned)gw * 32 + lane];
    } else {
        w = sigmoidf_(__ldg(ilw + layer));
        s = he[(unsigned)(gw - NU) * 32 + lane];
    }
    float iw = 1.0f - w;
    float2 o;
    o.x = w * acc.x + iw * s.x;
    o.y = w * acc.y + iw * s.y;
    out[(unsigned)gw * 32 + lane] = o;

    float2* ap = reinterpret_cast<float2*>(g_acc) + (unsigned)gw * 32 + lane;
    float2 a = *ap;
    a.x += o.x; a.y += o.y;
    *ap = a;
}

// ---------------------------------------------------------------------------
// gamma[b] = dot(acc[users[b]], acc[U+items[b]]) / (L+1)^2
// ---------------------------------------------------------------------------
__global__ void __launch_bounds__(256)
dot_kernel(const int* __restrict__ users,
           const int* __restrict__ items,
           float* __restrict__ out,
           int B) {
    int gid = blockIdx.x * blockDim.x + threadIdx.x;
    int w = gid >> 5;
    int lane = threadIdx.x & 31;
    if (w >= B) return;
    int u  = __ldg(users + w);
    int it = __ldg(items + w);
    const float2* up = reinterpret_cast<const float2*>(g_acc + (size_t)u * DD);
    const float2* ip = reinterpret_cast<const float2*>(g_acc + (size_t)(NU + it) * DD);
    float2 a = up[lane];
    float2 b = ip[lane];
    float s = a.x * b.x + a.y * b.y;
    #pragma unroll
    for (int o = 16; o > 0; o >>= 1)
        s += __shfl_down_sync(0xffffffffu, s, o);
    if (lane == 0) out[w] = s * (1.0f / ((NL + 1) * (NL + 1)));
}

// ---------------------------------------------------------------------------
// kernel_launch
// Inputs: 0 user_emb 1 item_emb 2 symptom_emb 3 herb_emb 4 user_lw 5 item_lw
//         6 edge_val 7 edge_row 8 edge_col 9 users 10 items -> gamma [B] f32
// ---------------------------------------------------------------------------
extern "C" void kernel_launch(void* const* d_in, const int* in_sizes, int n_in,
                              void* d_out, int out_size) {
    const float4* ue  = (const float4*)d_in[0];
    const float4* ie  = (const float4*)d_in[1];
    const float4* se4 = (const float4*)d_in[2];
    const float4* he4 = (const float4*)d_in[3];
    const float*  ulw = (const float*)d_in[4];
    const float*  ilw = (const float*)d_in[5];
    const float*  ev  = (const float*)d_in[6];
    const int*    er  = (const int*)d_in[7];
    const int*    ec  = (const int*)d_in[8];
    const int*    us  = (const int*)d_in[9];
    const int*    it  = (const int*)d_in[10];
    const float2* se2 = (const float2*)d_in[2];
    const float2* he2 = (const float2*)d_in[3];
    float* out = (float*)d_out;

    const int E = in_sizes[6];
    const int B = in_sizes[9];
    const int TB = 256;

    const int elem_threads = NN * (DD / 4);
    const int elem_blocks = (elem_threads + TB - 1) / TB;
    const int edge_blocks = (E + TB - 1) / TB;
    const int node_blocks = (NN + TB - 1) / TB;

    // layer-0 fusion (independent of CSR build; both feed the SpMM layers)
    fuse0_kernel<<<elem_blocks, TB>>>(ue, ie, se4, he4, ulw, ilw);

    // CSR build
    zero_counts_kernel<<<node_blocks, TB>>>();
    hist_kernel<<<edge_blocks, TB>>>(er, E);
    scan_reduce_kernel<<<NCHUNK, CHUNK>>>();
    scan_chunks_kernel<<<1, 32>>>(E);
    scan_final_kernel<<<NCHUNK, CHUNK>>>();
    permute_kernel<<<edge_blocks, TB>>>(ev, er, ec, E);

    // fused SpMM + fusion layers (ping-pong buffers)
    const int spmm_blocks = (NN * 32 + TB - 1) / TB;
    spmm_fuse_kernel<<<spmm_blocks, TB>>>(se2, he2, ulw, ilw, 1, 0); // A->B
    spmm_fuse_kernel<<<spmm_blocks, TB>>>(se2, he2, ulw, ilw, 2, 1); // B->A
    spmm_fuse_kernel<<<spmm_blocks, TB>>>(se2, he2, ulw, ilw, 3, 0); // A->B

    int dot_blocks = (B * 32 + TB - 1) / TB;
    dot_kernel<<<dot_blocks, TB>>>(us, it, out, B);
}

// round 16
// speedup vs baseline: 1.8398x; 1.1414x over previous
#include <cuda_runtime.h>
#include <cuda_bf16.h>
#include <cuda_fp16.h>

#define NU 100000
#define NI 100000
#define DD 64
#define NN (NU + NI)
#define NL 3
#define EMAX 6400000
#define CHUNK 1024
#define NCHUNK ((NN + CHUNK - 1) / CHUNK)   // 196

// Scratch (device globals per the allocation rules).
__device__ float  g_acc [(size_t)NN * DD];    // running layer sum (fp32)
__device__ __half2 g_hA[(size_t)NN * (DD/2)]; // half-precision ping
__device__ __half2 g_hB[(size_t)NN * (DD/2)]; // half-precision pong
__device__ __align__(16) int2 g_csr[EMAX];    // (col, val-bits) grouped by row
__device__ int   g_rowstart[NN + 1];
__device__ int   g_counts[NN];
__device__ int   g_cursor[NN];
__device__ int   g_chunkSum[NCHUNK];
__device__ int   g_chunkOff[NCHUNK];

__device__ __forceinline__ float sigmoidf_(float x) {
    return 1.0f / (1.0f + __expf(-x));
}

// ---------------------------------------------------------------------------
// Layer-0 semantic fusion: hA = half2(fuse(emb, side)), acc = fuse(emb, side).
// One thread per float2 (= one half2). NN*32 threads.
// ---------------------------------------------------------------------------
__global__ void __launch_bounds__(256)
fuse0_kernel(const float2* __restrict__ ue,
             const float2* __restrict__ ie,
             const float2* __restrict__ se,
             const float2* __restrict__ he,
             const float* __restrict__ ulw,
             const float* __restrict__ ilw) {
    int i = blockIdx.x * blockDim.x + threadIdx.x;
    const int total = NN * (DD / 2);
    if (i >= total) return;
    int row = i >> 5;   // 32 half2 per row
    float2 x, s;
    float w;
    if (row < NU) {
        w = sigmoidf_(ulw[0]);
        x = ue[i];
        s = se[i];
    } else {
        w = sigmoidf_(ilw[0]);
        int j = i - NU * (DD / 2);
        x = ie[j];
        s = he[j];
    }
    float iw = 1.0f - w;
    float2 o;
    o.x = w * x.x + iw * s.x;
    o.y = w * x.y + iw * s.y;
    reinterpret_cast<float2*>(g_acc)[i] = o;
    g_hA[i] = __float22half2_rn(o);
}

// ---------------------------------------------------------------------------
// CSR build, step 0: zero counts + cursors.
// ---------------------------------------------------------------------------
__global__ void __launch_bounds__(256)
zero_counts_kernel() {
    int i = blockIdx.x * blockDim.x + threadIdx.x;
    if (i < NN) { g_counts[i] = 0; g_cursor[i] = 0; }
}

// ---------------------------------------------------------------------------
// CSR build, step 1: histogram of edge rows.
// ---------------------------------------------------------------------------
__global__ void __launch_bounds__(256)
hist_kernel(const int* __restrict__ er, int E) {
    int e = blockIdx.x * blockDim.x + threadIdx.x;
    if (e >= E) return;
    atomicAdd(&g_counts[__ldcs(er + e)], 1);
}

// ---------------------------------------------------------------------------
// CSR build, step 2a: per-chunk sums.
// ---------------------------------------------------------------------------
__global__ void __launch_bounds__(CHUNK)
scan_reduce_kernel() {
    __shared__ int sh[CHUNK];
    int tid = threadIdx.x;
    int i = blockIdx.x * CHUNK + tid;
    sh[tid] = (i < NN) ? g_counts[i] : 0;
    __syncthreads();
    #pragma unroll
    for (int s = CHUNK / 2; s > 0; s >>= 1) {
        if (tid < s) sh[tid] += sh[tid + s];
        __syncthreads();
    }
    if (tid == 0) g_chunkSum[blockIdx.x] = sh[0];
}

// ---------------------------------------------------------------------------
// CSR build, step 2b: exclusive scan of 196 chunk sums (one block, parallel).
// ---------------------------------------------------------------------------
__global__ void __launch_bounds__(256)
scan_chunks_kernel(int E) {
    __shared__ int sh[256];
    int tid = threadIdx.x;
    int x = (tid < NCHUNK) ? g_chunkSum[tid] : 0;
    sh[tid] = x;
    __syncthreads();
    #pragma unroll
    for (int off = 1; off < 256; off <<= 1) {
        int t = (tid >= off) ? sh[tid - off] : 0;
        __syncthreads();
        sh[tid] += t;
        __syncthreads();
    }
    if (tid < NCHUNK) g_chunkOff[tid] = sh[tid] - x;   // exclusive
    if (tid == 0) g_rowstart[NN] = E;
}

// ---------------------------------------------------------------------------
// CSR build, step 2c: intra-chunk exclusive scan + chunk offset -> rowstart.
// ---------------------------------------------------------------------------
__global__ void __launch_bounds__(CHUNK)
scan_final_kernel() {
    __shared__ int sh[CHUNK];
    int tid = threadIdx.x;
    int i = blockIdx.x * CHUNK + tid;
    int x = (i < NN) ? g_counts[i] : 0;
    sh[tid] = x;
    __syncthreads();
    #pragma unroll
    for (int off = 1; off < CHUNK; off <<= 1) {
        int t = (tid >= off) ? sh[tid - off] : 0;
        __syncthreads();
        sh[tid] += t;
        __syncthreads();
    }
    if (i < NN) g_rowstart[i] = sh[tid] - x + g_chunkOff[blockIdx.x];
}

// ---------------------------------------------------------------------------
// CSR build, step 3: permute (col,val) into row-grouped order.
// ---------------------------------------------------------------------------
__global__ void __launch_bounds__(256)
permute_kernel(const float* __restrict__ ev,
               const int* __restrict__ er,
               const int* __restrict__ ec,
               int E) {
    int e = blockIdx.x * blockDim.x + threadIdx.x;
    if (e >= E) return;
    int r = __ldcs(er + e);
    int slot = atomicAdd(&g_cursor[r], 1);
    int pos = g_rowstart[r] + slot;
    g_csr[pos] = make_int2(__ldcs(ec + e), __float_as_int(__ldcs(ev + e)));
}

// ---------------------------------------------------------------------------
// Fused CSR SpMM + semantic fusion + acc update. fp16 gather, fp32 math.
// One warp per row; lane owns dims [2*lane, 2*lane+1] (one half2 = 4B,
// so each edge-gather is a single 128B wavefront). CSR metadata is read
// two edges at a time via int4 broadcast loads (halves metadata wavefronts).
// parity 0: in = hA, out = hB; parity 1: swapped.
// ---------------------------------------------------------------------------
__global__ void __launch_bounds__(256)
spmm_fuse_kernel(const float2* __restrict__ se,
                 const float2* __restrict__ he,
                 const float* __restrict__ ulw,
                 const float* __restrict__ ilw,
                 int layer, int parity) {
    int gw = (blockIdx.x * blockDim.x + threadIdx.x) >> 5;
    if (gw >= NN) return;
    int lane = threadIdx.x & 31;

    const __half2* in  = parity ? g_hB : g_hA;
    __half2*       out = parity ? g_hA : g_hB;

    int beg = g_rowstart[gw];
    int end = g_rowstart[gw + 1];

    float2 acc = make_float2(0.f, 0.f);
    int j = beg;

    // head: align j to even index for int4 (16B) CSR loads
    if ((j & 1) && j < end) {
        int2 a = g_csr[j];
        float2 x = __half22float2(__ldg(in + (unsigned)a.x * 32 + lane));
        float v = __int_as_float(a.y);
        acc.x += v * x.x; acc.y += v * x.y;
        j++;
    }

    const int4* csr4 = reinterpret_cast<const int4*>(g_csr);
    // main loop: 4 edges per iteration via two int4 loads
    for (; j + 4 <= end; j += 4) {
        int4 p0 = csr4[(j >> 1)];        // edges j, j+1
        int4 p1 = csr4[(j >> 1) + 1];    // edges j+2, j+3
        float2 x0 = __half22float2(__ldg(in + (unsigned)p0.x * 32 + lane));
        float2 x1 = __half22float2(__ldg(in + (unsigned)p0.z * 32 + lane));
        float2 x2 = __half22float2(__ldg(in + (unsigned)p1.x * 32 + lane));
        float2 x3 = __half22float2(__ldg(in + (unsigned)p1.z * 32 + lane));
        float v0 = __int_as_float(p0.y), v1 = __int_as_float(p0.w);
        float v2 = __int_as_float(p1.y), v3 = __int_as_float(p1.w);
        acc.x += v0 * x0.x; acc.y += v0 * x0.y;
        acc.x += v1 * x1.x; acc.y += v1 * x1.y;
        acc.x += v2 * x2.x; acc.y += v2 * x2.y;
        acc.x += v3 * x3.x; acc.y += v3 * x3.y;
    }
    // tail
    for (; j < end; j++) {
        int2 a = g_csr[j];
        float2 x = __half22float2(__ldg(in + (unsigned)a.x * 32 + lane));
        float v = __int_as_float(a.y);
        acc.x += v * x.x; acc.y += v * x.y;
    }

    // semantic fusion epilogue
    float w;
    float2 s;
    if (gw < NU) {
        w = sigmoidf_(__ldg(ulw + layer));
        s = se[(unsigned)gw * 32 + lane];
    } else {
        w = sigmoidf_(__ldg(ilw + layer));
        s = he[(unsigned)(gw - NU) * 32 + lane];
    }
    float iw = 1.0f - w;
    float2 o;
    o.x = w * acc.x + iw * s.x;
    o.y = w * acc.y + iw * s.y;
    if (layer < NL)
        out[(unsigned)gw * 32 + lane] = __float22half2_rn(o);

    float2* ap = reinterpret_cast<float2*>(g_acc) + (unsigned)gw * 32 + lane;
    float2 a = *ap;
    a.x += o.x; a.y += o.y;
    *ap = a;
}

// ---------------------------------------------------------------------------
// gamma[b] = dot(acc[users[b]], acc[U+items[b]]) / (L+1)^2
// ---------------------------------------------------------------------------
__global__ void __launch_bounds__(256)
dot_kernel(const int* __restrict__ users,
           const int* __restrict__ items,
           float* __restrict__ out,
           int B) {
    int gid = blockIdx.x * blockDim.x + threadIdx.x;
    int w = gid >> 5;
    int lane = threadIdx.x & 31;
    if (w >= B) return;
    int u  = __ldg(users + w);
    int it = __ldg(items + w);
    const float2* up = reinterpret_cast<const float2*>(g_acc + (size_t)u * DD);
    const float2* ip = reinterpret_cast<const float2*>(g_acc + (size_t)(NU + it) * DD);
    float2 a = up[lane];
    float2 b = ip[lane];
    float s = a.x * b.x + a.y * b.y;
    #pragma unroll
    for (int o = 16; o > 0; o >>= 1)
        s += __shfl_down_sync(0xffffffffu, s, o);
    if (lane == 0) out[w] = s * (1.0f / ((NL + 1) * (NL + 1)));
}

// ---------------------------------------------------------------------------
// kernel_launch
// Inputs: 0 user_emb 1 item_emb 2 symptom_emb 3 herb_emb 4 user_lw 5 item_lw
//         6 edge_val 7 edge_row 8 edge_col 9 users 10 items -> gamma [B] f32
// ---------------------------------------------------------------------------
extern "C" void kernel_launch(void* const* d_in, const int* in_sizes, int n_in,
                              void* d_out, int out_size) {
    const float2* ue  = (const float2*)d_in[0];
    const float2* ie  = (const float2*)d_in[1];
    const float2* se2 = (const float2*)d_in[2];
    const float2* he2 = (const float2*)d_in[3];
    const float*  ulw = (const float*)d_in[4];
    const float*  ilw = (const float*)d_in[5];
    const float*  ev  = (const float*)d_in[6];
    const int*    er  = (const int*)d_in[7];
    const int*    ec  = (const int*)d_in[8];
    const int*    us  = (const int*)d_in[9];
    const int*    it  = (const int*)d_in[10];
    float* out = (float*)d_out;

    const int E = in_sizes[6];
    const int B = in_sizes[9];
    const int TB = 256;

    const int elem_threads = NN * (DD / 2);
    const int elem_blocks = (elem_threads + TB - 1) / TB;
    const int edge_blocks = (E + TB - 1) / TB;
    const int node_blocks = (NN + TB - 1) / TB;

    // layer-0 fusion (independent of CSR build; both feed the SpMM layers)
    fuse0_kernel<<<elem_blocks, TB>>>(ue, ie, se2, he2, ulw, ilw);

    // CSR build
    zero_counts_kernel<<<node_blocks, TB>>>();
    hist_kernel<<<edge_blocks, TB>>>(er, E);
    scan_reduce_kernel<<<NCHUNK, CHUNK>>>();
    scan_chunks_kernel<<<1, 256>>>(E);
    scan_final_kernel<<<NCHUNK, CHUNK>>>();
    permute_kernel<<<edge_blocks, TB>>>(ev, er, ec, E);

    // fused SpMM + fusion layers (ping-pong half buffers)
    const int spmm_blocks = (NN * 32 + TB - 1) / TB;
    spmm_fuse_kernel<<<spmm_blocks, TB>>>(se2, he2, ulw, ilw, 1, 0); // hA->hB
    spmm_fuse_kernel<<<spmm_blocks, TB>>>(se2, he2, ulw, ilw, 2, 1); // hB->hA
    spmm_fuse_kernel<<<spmm_blocks, TB>>>(se2, he2, ulw, ilw, 3, 0); // hA->hB

    int dot_blocks = (B * 32 + TB - 1) / TB;
    dot_kernel<<<dot_blocks, TB>>>(us, it, out, B);
}